// round 15
// baseline (speedup 1.0000x reference)
#include <cuda_runtime.h>

// VideoEmbedding: out[n,d] = sum_k basis(t_n)[k] * W[vid_n, d, k]
// N=400000, D=64, K=13, V=128.
//
// SINGLE persistent kernel, single co-resident wave:
//  Phase A: weight transpose + per-block smem-rank histogram (ranks in regs)
//  barrier1
//  Phase S: block v scans video v's count row -> per-block bases (O(G*V))
//  barrier2
//  Phase C: own bases + 32-padded segment scan + scatter to g_sorted
//  barrier3
//  Phase B: half-warp scheme — lane owns 4 output cols, halves take
//           alternate j. R12 killed the L1 wall with shfl broadcast;
//           R13/R14 showed the residual is NOT latency (ILP + prefetch both
//           neutral) -> SHFL crossbar throughput is the binder (13/step).
//           Fix: broadcast only idx,s1,q1 (3 SHFLs); each lane recomputes
//           the double-angle recurrence (10 scalar FMAs, identical values)
//           and re-splats. Trades crossbar ops for idle fma-pipe slots.

static constexpr int D  = 64;
static constexpr int K  = 13;
static constexpr int MAXV = 256;
static constexpr int SORT_CAP = 1 << 20;
static constexpr int GMAX = 1024;
static constexpr int TPB  = 256;
static constexpr int NU   = 4;     // int4 slots per thread in phase A

__device__ float g_wt[MAXV * K * D];
__device__ int   g_cnt[MAXV * GMAX];    // [v][b]
__device__ int   g_base[GMAX * MAXV];   // [b][v] scatter bases (pre-segoff)
__device__ int   g_segtot[MAXV];
__device__ int   g_sorted[SORT_CAP];    // never-written pad slots stay 0
__device__ int   g_bar, g_fin;

typedef unsigned long long ull;

__device__ __forceinline__ ull ffma2u(ull a, ull b, ull c) {
    ull d;
    asm("fma.rn.f32x2 %0, %1, %2, %3;" : "=l"(d) : "l"(a), "l"(b), "l"(c));
    return d;
}
__device__ __forceinline__ ull fmul2u(ull a, ull b) {
    ull d;
    asm("mul.rn.f32x2 %0, %1, %2;" : "=l"(d) : "l"(a), "l"(b));
    return d;
}
__device__ __forceinline__ ull fadd2u(ull a, ull b) {
    ull d;
    asm("add.rn.f32x2 %0, %1, %2;" : "=l"(d) : "l"(a), "l"(b));
    return d;
}
__device__ __forceinline__ ull splat2(float x) {
    ull r;
    asm("mov.b64 %0, {%1, %1};" : "=l"(r) : "f"(x));
    return r;
}

__device__ __forceinline__ void grid_barrier(int tid, int target) {
    __threadfence();
    __syncthreads();
    if (tid == 0) {
        atomicAdd(&g_bar, 1);
        volatile int* vb = &g_bar;
        while (*vb < target) __nanosleep(32);
    }
    __syncthreads();
}

__global__ void __launch_bounds__(TPB, 2)
k_all(const float* __restrict__ w, const int* __restrict__ vids,
      const float* __restrict__ times, float* __restrict__ out,
      int N, int V, int tile, int G) {
    __shared__ int s_rk[MAXV];        // rank counters -> scan scratch
    __shared__ int s_base[MAXV];      // this block's scatter bases
    __shared__ int s_start[MAXV + 1]; // padded segment starts (+ total)
    __shared__ int s_end[MAXV];       // real segment ends
    __shared__ int s_scan[TPB];       // phase-S block-scan scratch

    const int tid = threadIdx.x, b = blockIdx.x;
    for (int i = tid; i < MAXV; i += TPB) s_rk[i] = 0;
    __syncthreads();

    // ---- Phase A: transpose [v][d][k] -> [v][k][d] ----
    const int total = V * D * K;
    for (int i = b * TPB + tid; i < total; i += G * TPB) {
        int k = i % K;
        int d = (i / K) % D;
        int v = i / (K * D);
        g_wt[(v * K + k) * D + d] = w[i];
    }

    // ---- Phase A: histogram, ranks held in registers ----
    const int start = b * tile;               // tile is 4-aligned
    const int end   = min(start + tile, N);
    const int s4 = start >> 2, e4 = end >> 2;
    int4 q[NU]; int rk[NU][4]; bool hv[NU];
#pragma unroll
    for (int u = 0; u < NU; u++) {
        const int i4 = s4 + u * TPB + tid;
        hv[u] = (i4 < e4);
        if (hv[u]) {
            q[u] = reinterpret_cast<const int4*>(vids)[i4];
            rk[u][0] = atomicAdd(&s_rk[q[u].x], 1);
            rk[u][1] = atomicAdd(&s_rk[q[u].y], 1);
            rk[u][2] = atomicAdd(&s_rk[q[u].z], 1);
            rk[u][3] = atomicAdd(&s_rk[q[u].w], 1);
        }
    }
    int tval = -1, trk = 0;
    const int ti = (e4 << 2) + tid;
    if (ti < end) { tval = vids[ti]; trk = atomicAdd(&s_rk[tval], 1); }
    __syncthreads();

    for (int i = tid; i < V; i += TPB)
        g_cnt[i * GMAX + b] = s_rk[i];

    grid_barrier(tid, G);

    // ---- Phase S: block v scans video v's count row (cooperative) ----
    for (int v = b; v < V; v += G) {
        int4 c = make_int4(0, 0, 0, 0);
        const int bb = tid * 4;
        if (bb < G)
            c = *reinterpret_cast<const int4*>(g_cnt + v * GMAX + bb);
        const int lsum = c.x + c.y + c.z + c.w;
        s_scan[tid] = lsum;
        __syncthreads();
        for (int s = 1; s < TPB; s <<= 1) {       // inclusive block scan
            int a = (tid >= s) ? s_scan[tid - s] : 0;
            __syncthreads();
            s_scan[tid] += a;
            __syncthreads();
        }
        int excl = s_scan[tid] - lsum;
        if (bb < G) {
            g_base[(bb    ) * MAXV + v] = excl;
            g_base[(bb + 1) * MAXV + v] = excl + c.x;
            g_base[(bb + 2) * MAXV + v] = excl + c.x + c.y;
            g_base[(bb + 3) * MAXV + v] = excl + c.x + c.y + c.z;
        }
        if (tid == TPB - 1) g_segtot[v] = s_scan[tid];
        __syncthreads();
    }

    grid_barrier(tid, 2 * G);

    // ---- Phase C: own bases + padded segment scan + scatter ----
    int totv = 0;
    if (tid < MAXV) {
        totv = (tid < V) ? g_segtot[tid] : 0;
        s_rk[tid] = (totv + 31) & ~31;
    }
    __syncthreads();
    for (int s = 1; s < MAXV; s <<= 1) {          // inclusive scan over videos
        int a = (tid < MAXV && tid >= s) ? s_rk[tid - s] : 0;
        __syncthreads();
        if (tid < MAXV) s_rk[tid] += a;
        __syncthreads();
    }
    if (tid < MAXV) {
        const int pad = (totv + 31) & ~31;
        const int segoff = s_rk[tid] - pad;       // exclusive padded offset
        s_start[tid] = segoff;
        s_end[tid]   = segoff + totv;
        if (tid < V) s_base[tid] = segoff + g_base[b * MAXV + tid];
        if (tid == MAXV - 1) s_start[MAXV] = s_rk[tid];
    }
    __syncthreads();
    const int NC = s_start[MAXV] >> 5;

#pragma unroll
    for (int u = 0; u < NU; u++) {
        if (hv[u]) {
            const int base = (s4 + u * TPB + tid) << 2;
            g_sorted[s_base[q[u].x] + rk[u][0]] = base;
            g_sorted[s_base[q[u].y] + rk[u][1]] = base + 1;
            g_sorted[s_base[q[u].z] + rk[u][2]] = base + 2;
            g_sorted[s_base[q[u].w] + rk[u][3]] = base + 3;
        }
    }
    if (tval >= 0) g_sorted[s_base[tval] + trk] = ti;

    grid_barrier(tid, 3 * G);

    // ---- Phase B: half-warp, 4 cols/lane, 3-shfl broadcast + recompute ----
    const int lane = tid & 31;
    const int wib  = tid >> 5;
    const int half = lane >> 4;            // 0: even j, 1: odd j
    const int c4   = (lane & 15) * 4;      // 4 owned output columns
    const int gwarp = b * 8 + wib;
    const int TW = G * 8;
    const int L = (NC + TW - 1) / TW;
    const int cbeg = gwarp * L;
    const int cend = min(cbeg + L, NC);

    if (cbeg < cend) {
        int v = 0;
        {
            const int pos = cbeg * 32;
#pragma unroll
            for (int step = 128; step; step >>= 1) {
                const int nv = v + step;
                if (nv <= MAXV - 1 && s_start[nv] <= pos) v = nv;
            }
        }
        int vprev = -1;
        ull wA[K], wB[K];

        // prologue loads for the first chunk
        int   idx = g_sorted[cbeg * 32 + lane];   // pad slots are 0 (valid)
        float t   = times[idx];

        for (int c = cbeg; c < cend; c++) {
            const int pos = c * 32;
            while (pos >= s_start[v + 1]) v++;     // warp-uniform walk

            if (v != vprev) {
                const float* wp = g_wt + v * (K * D) + c4;
#pragma unroll
                for (int k = 0; k < K; k++) {
                    ulonglong2 u =
                        *reinterpret_cast<const ulonglong2*>(wp + k * D);
                    wA[k] = u.x; wB[k] = u.y;
                }
                vprev = v;
            }

            // only s1,q1 for this lane's own n — rest recomputed per step
            const float ang = t * 3.14159265358979323846f;
            float s1, q1; __sincosf(ang, &s1, &q1);

            // software pipeline: next chunk's dependent load chain
            int   idx_nx = 0;
            float t_nx   = 0.f;
            if (c + 1 < cend) {
                idx_nx = g_sorted[pos + 32 + lane];
                t_nx   = times[idx_nx];
            }

            const unsigned m = 0xffffffffu;
            const int jmax  = min(32, s_end[v] - pos);   // >= 1, warp-uniform
            const int jpmax = (jmax + 1) >> 1;

            for (int jp = 0; jp < jpmax; jp++) {
                const int j0 = 2 * jp + half;            // per-half source n
                // ONLY 3 crossbar ops per step (was 13)
                const int   nn  = __shfl_sync(m, idx, j0);
                const float bs1 = __shfl_sync(m, s1, j0);
                const float bq1 = __shfl_sync(m, q1, j0);
                // recompute recurrence per lane (identical values, fma pipe)
                const float bs2 = 2.f * bs1 * bq1;
                const float bq2 = fmaf(bq1, bq1, -bs1 * bs1);
                const float bs3 = 2.f * bs2 * bq2;
                const float bq3 = fmaf(bq2, bq2, -bs2 * bs2);
                const float bs4 = 2.f * bs3 * bq3;
                const float bq4 = fmaf(bq3, bq3, -bs3 * bs3);
                const float bs5 = 2.f * bs4 * bq4;
                const float bq5 = fmaf(bq4, bq4, -bs4 * bs4);
                const float bs6 = 2.f * bs5 * bq5;
                const float bq6 = fmaf(bq5, bq5, -bs5 * bs5);

                const ull B1  = splat2(bs1);
                const ull B2  = splat2(bs2);
                const ull B3  = splat2(bs3);
                const ull B4  = splat2(bs4);
                const ull B5  = splat2(bs5);
                const ull B6  = splat2(bs6);
                const ull B7  = splat2(bq1);
                const ull B8  = splat2(bq2);
                const ull B9  = splat2(bq3);
                const ull B10 = splat2(bq4);
                const ull B11 = splat2(bq5);
                const ull B12 = splat2(bq6);

                ull a0 = ffma2u(B1, wA[1], wA[0]);       // basis[0] == 1
                ull a1 = fmul2u(B2, wA[2]);
                a0 = ffma2u(B3,  wA[3],  a0);
                a1 = ffma2u(B4,  wA[4],  a1);
                a0 = ffma2u(B5,  wA[5],  a0);
                a1 = ffma2u(B6,  wA[6],  a1);
                a0 = ffma2u(B7,  wA[7],  a0);
                a1 = ffma2u(B8,  wA[8],  a1);
                a0 = ffma2u(B9,  wA[9],  a0);
                a1 = ffma2u(B10, wA[10], a1);
                a0 = ffma2u(B11, wA[11], a0);
                a1 = ffma2u(B12, wA[12], a1);
                ull b0 = ffma2u(B1, wB[1], wB[0]);
                ull b1 = fmul2u(B2, wB[2]);
                b0 = ffma2u(B3,  wB[3],  b0);
                b1 = ffma2u(B4,  wB[4],  b1);
                b0 = ffma2u(B5,  wB[5],  b0);
                b1 = ffma2u(B6,  wB[6],  b1);
                b0 = ffma2u(B7,  wB[7],  b0);
                b1 = ffma2u(B8,  wB[8],  b1);
                b0 = ffma2u(B9,  wB[9],  b0);
                b1 = ffma2u(B10, wB[10], b1);
                b0 = ffma2u(B11, wB[11], b0);
                b1 = ffma2u(B12, wB[12], b1);
                if (j0 < jmax) {
                    *reinterpret_cast<ulonglong2*>(out + (long)nn * D + c4) =
                        make_ulonglong2(fadd2u(a0, a1), fadd2u(b0, b1));
                }
            }

            idx = idx_nx;          // rotate pipeline
            t   = t_nx;
        }
    }

    // ---- exit ticket: reset barrier counters for next graph replay ----
    __threadfence();
    if (tid == 0) {
        if (atomicAdd(&g_fin, 1) == G - 1) { g_bar = 0; g_fin = 0; }
    }
}

extern "C" void kernel_launch(void* const* d_in, const int* in_sizes, int n_in,
                              void* d_out, int out_size) {
    const float* times   = (const float*)d_in[0];
    const int*   vids    = (const int*)d_in[1];
    const float* weights = (const float*)d_in[2];
    float*       out     = (float*)d_out;

    const int N = in_sizes[0];
    int V = in_sizes[2] / (D * K);
    if (V > MAXV) V = MAXV;

    int dev = 0;
    cudaGetDevice(&dev);
    int sms = 148;
    cudaDeviceGetAttribute(&sms, cudaDevAttrMultiProcessorCount, dev);
    int nb = 0;
    cudaOccupancyMaxActiveBlocksPerMultiprocessor(&nb, k_all, TPB, 0);
    if (nb < 1) nb = 1;
    int G = nb * sms;
    if (G > GMAX) G = GMAX;
    G &= ~3;                                  // multiple of 4 (int4 row reads)

    const int tile = (((N + G - 1) / G) + 3) & ~3;   // 4-aligned
    k_all<<<G, TPB>>>(weights, vids, times, out, N, V, tile, G);
}